// round 14
// baseline (speedup 1.0000x reference)
#include <cuda_runtime.h>
#include <math.h>
#include <stdint.h>

// Problem constants
#define B_ 8
#define T_ 2048
#define C_ 384
#define H_ 6
#define D_ 64
#define M_ (B_*T_)          // 16384 rows
#define HALF_ 32            // D/2
#define MC_ (M_*C_)
#define CC_ (C_*C_)

// ---------------- tf32 helpers ----------------
__device__ __forceinline__ unsigned cvt_tf32(float x) {
    unsigned u;
    asm("cvt.rna.tf32.f32 %0, %1;" : "=r"(u) : "f"(x));
    return u;
}
__device__ __forceinline__ float tf32f(float x) {
    return __uint_as_float(cvt_tf32(x));
}
__device__ __forceinline__ float ex2f(float x) {
    float y;
    asm("ex2.approx.f32 %0, %1;" : "=f"(y) : "f"(x));
    return y;
}
__device__ __forceinline__ void mma8(float c[4], const unsigned a[4],
                                     unsigned b0, unsigned b1) {
    asm volatile(
        "mma.sync.aligned.m16n8k8.row.col.f32.tf32.tf32.f32 "
        "{%0,%1,%2,%3}, {%4,%5,%6,%7}, {%8,%9}, {%0,%1,%2,%3};"
        : "+f"(c[0]), "+f"(c[1]), "+f"(c[2]), "+f"(c[3])
        : "r"(a[0]), "r"(a[1]), "r"(a[2]), "r"(a[3]), "r"(b0), "r"(b1));
}
__device__ __forceinline__ void cp16(uint32_t dst, const void* src) {
    asm volatile("cp.async.cg.shared.global [%0], [%1], 16;" :: "r"(dst), "l"(src));
}
#define CP_COMMIT() asm volatile("cp.async.commit_group;" ::: "memory")
#define CP_WAIT1()  asm volatile("cp.async.wait_group 1;"  ::: "memory")
#define CP_WAIT0()  asm volatile("cp.async.wait_group 0;"  ::: "memory")
__device__ __forceinline__ uint32_t smem_to_u32(const void* p) {
    uint32_t a;
    asm("{ .reg .u64 t; cvta.to.shared.u64 t, %1; cvt.u32.u64 %0, t; }"
        : "=r"(a) : "l"(p));
    return a;
}

// ---------------- scratch ----------------
__device__ float g_xc[(size_t)MC_];          // tf32-rounded x
__device__ float g_w3[(size_t)3*CC_];        // tf32-rounded Wq,Wk,Wv stacked
__device__ float g_wo[(size_t)CC_];          // tf32-rounded Wo
__device__ float g_qh[(size_t)B_*H_*T_*D_];  // [bh][t][dperm]
__device__ float g_kh[(size_t)B_*H_*T_*D_];  // [bh][t][dperm]
__device__ float g_vh[(size_t)B_*H_*T_*D_];  // TRANSPOSED: [bh][d][keyperm]
__device__ float g_yt[(size_t)MC_];          // attention out (tf32-rounded)

// ---------------- elementwise tf32 pre-convert ----------------
__global__ __launch_bounds__(256) void cvt_kernel(const float4* __restrict__ src,
                                                  float4* __restrict__ dst, int n4)
{
    const int i = blockIdx.x * blockDim.x + threadIdx.x;
    if (i < n4) {
        const float4 v = src[i];
        dst[i] = make_float4(tf32f(v.x), tf32f(v.y), tf32f(v.z), tf32f(v.w));
    }
}

__global__ __launch_bounds__(256) void cvt4_kernel(const float4* __restrict__ s0,
                                                   const float4* __restrict__ s1,
                                                   const float4* __restrict__ s2,
                                                   const float4* __restrict__ s3,
                                                   float4* __restrict__ d0,
                                                   float4* __restrict__ d1,
                                                   float4* __restrict__ d2,
                                                   float4* __restrict__ d3,
                                                   int n4)
{
    const int i = blockIdx.x * blockDim.x + threadIdx.x;
    if (i < n4) {
        float4 v;
        v = s0[i]; d0[i] = make_float4(tf32f(v.x), tf32f(v.y), tf32f(v.z), tf32f(v.w));
        v = s1[i]; d1[i] = make_float4(tf32f(v.x), tf32f(v.y), tf32f(v.z), tf32f(v.w));
        v = s2[i]; d2[i] = make_float4(tf32f(v.x), tf32f(v.y), tf32f(v.z), tf32f(v.w));
        v = s3[i]; d3[i] = make_float4(tf32f(v.x), tf32f(v.y), tf32f(v.z), tf32f(v.w));
    }
}

// ---------------- pipelined tf32 GEMM with fused rope/rms epilogue ----------------
#define TBK 32
#define NCH (C_ / TBK)          // 12
#define SSTR 36
#define STAGE_BYTES (128 * SSTR * 4)          // 18432
#define GA_OFF(st) ((st) * STAGE_BYTES)
#define GB_OFF(st) (2 * STAGE_BYTES + (st) * STAGE_BYTES)
#define GSMEM (4 * STAGE_BYTES)               // 73728

__global__ __launch_bounds__(128) void gemm_pipe(const float* __restrict__ A,
                                                 const float* __restrict__ W,
                                                 float* __restrict__ Cb,
                                                 const float* __restrict__ cosp,
                                                 const float* __restrict__ sinp,
                                                 int wstride, int mode_base)
{
    extern __shared__ char smem[];
    const uint32_t smem_base = smem_to_u32(smem);

    const int tid  = threadIdx.x;
    const int w    = tid >> 5;
    const int lane = tid & 31;
    const int gr   = lane >> 2;
    const int gc   = lane & 3;
    const int wm   = w >> 1;
    const int wn   = w & 1;

    const int m0 = blockIdx.y * 128;
    const int n0 = blockIdx.x * 128;
    const int z  = blockIdx.z;
    const int mode = (mode_base == 3) ? 3 : z;
    const float* Wz = W + (size_t)z * wstride;

    float acc[4][8][4];
#pragma unroll
    for (int i = 0; i < 4; i++)
#pragma unroll
        for (int j = 0; j < 8; j++)
#pragma unroll
            for (int r = 0; r < 4; r++) acc[i][j][r] = 0.f;

    auto issue = [&](int ch, int st) {
#pragma unroll
        for (int p = 0; p < 8; p++) {
            const int idx = p * 128 + tid;
            const int r = idx >> 3;
            const int s = idx & 7;
            const uint32_t doff = r * (SSTR * 4) + s * 16;
            cp16(smem_base + GA_OFF(st) + doff,
                 A  + (size_t)(m0 + r) * C_ + ch * TBK + s * 4);
            cp16(smem_base + GB_OFF(st) + doff,
                 Wz + (size_t)(n0 + r) * C_ + ch * TBK + s * 4);
        }
    };

    issue(0, 0); CP_COMMIT();

    for (int ch = 0; ch < NCH; ch++) {
        const int st = ch & 1;
        if (ch + 1 < NCH) { issue(ch + 1, st ^ 1); CP_COMMIT(); CP_WAIT1(); }
        else              { CP_WAIT0(); }
        __syncthreads();

        const unsigned* sAf = (const unsigned*)(smem + GA_OFF(st));
        const unsigned* sBf = (const unsigned*)(smem + GB_OFF(st));

#pragma unroll
        for (int s = 0; s < 4; s++) {
            unsigned a[4][4];
#pragma unroll
            for (int i = 0; i < 4; i++) {
                const int row = wm * 64 + i * 16 + gr;
                a[i][0] = sAf[row * SSTR + s * 8 + gc];
                a[i][1] = sAf[(row + 8) * SSTR + s * 8 + gc];
                a[i][2] = sAf[row * SSTR + s * 8 + gc + 4];
                a[i][3] = sAf[(row + 8) * SSTR + s * 8 + gc + 4];
            }
            unsigned b[8][2];
#pragma unroll
            for (int j = 0; j < 8; j++) {
                const int row = wn * 64 + j * 8 + gr;
                b[j][0] = sBf[row * SSTR + s * 8 + gc];
                b[j][1] = sBf[row * SSTR + s * 8 + gc + 4];
            }
#pragma unroll
            for (int i = 0; i < 4; i++)
#pragma unroll
                for (int j = 0; j < 8; j++)
                    mma8(acc[i][j], a[i], b[j][0], b[j][1]);
        }
        __syncthreads();
    }

    // ---------------- epilogue ----------------
    if (mode == 3) {
#pragma unroll
        for (int i = 0; i < 4; i++) {
#pragma unroll
            for (int j = 0; j < 8; j++) {
                const int r  = m0 + wm * 64 + i * 16 + gr;
                const int cc = n0 + wn * 64 + j * 8 + gc * 2;
                *(float2*)(Cb + (size_t)r * C_ + cc)       = make_float2(acc[i][j][0], acc[i][j][1]);
                *(float2*)(Cb + (size_t)(r + 8) * C_ + cc) = make_float2(acc[i][j][2], acc[i][j][3]);
            }
        }
        return;
    }

    const int h = (n0 + wn * 64) >> 6;
    const float qsc = 0.125f * 1.44269504088896340736f;
    const int pa  = (gc < 2) ? (4 * gc)     : (4 * gc - 7);  // pi(2gc)
    const int pb_ = (gc < 2) ? (4 * gc + 2) : (4 * gc - 5);  // pi(2gc+1)
    const int pgr = (gr < 4) ? (2 * gr) : (2 * gr - 7);      // pi(gr)

#pragma unroll
    for (int i = 0; i < 4; i++) {
#pragma unroll
        for (int sub = 0; sub < 2; sub++) {
            const int r = m0 + wm * 64 + i * 16 + gr + sub * 8;
            const int b = r / T_;
            const int t = r - b * T_;
            const int e0 = sub * 2;

            if (mode == 2) {
                const int U = (t - gr) + pgr;
                float* vb2 = g_vh + (size_t)(b * H_ + h) * D_ * T_;
#pragma unroll
                for (int j = 0; j < 8; j++) {
                    const int d = j * 8 + 2 * gc;
                    vb2[(size_t)d * T_ + U]       = tf32f(acc[i][j][e0]);
                    vb2[(size_t)(d + 1) * T_ + U] = tf32f(acc[i][j][e0 + 1]);
                }
            } else {
                float* dst = (mode == 0) ? g_qh : g_kh;
                float* drow = dst + ((size_t)(b * H_ + h) * T_ + t) * D_;
                float y1[4][2], y2[4][2];
                float ss = 0.f;
#pragma unroll
                for (int j = 0; j < 4; j++) {
                    const int d = j * 8 + 2 * gc;
                    const float c0 = cosp[t * HALF_ + d];
                    const float c1 = cosp[t * HALF_ + d + 1];
                    const float s0 = sinp[t * HALF_ + d];
                    const float s1 = sinp[t * HALF_ + d + 1];
                    const float x10 = acc[i][j][e0],     x11 = acc[i][j][e0 + 1];
                    const float x20 = acc[i][j + 4][e0], x21 = acc[i][j + 4][e0 + 1];
                    y1[j][0] =  x10 * c0 + x20 * s0;
                    y1[j][1] =  x11 * c1 + x21 * s1;
                    y2[j][0] = -x10 * s0 + x20 * c0;
                    y2[j][1] = -x11 * s1 + x21 * c1;
                    ss += y1[j][0]*y1[j][0] + y1[j][1]*y1[j][1]
                        + y2[j][0]*y2[j][0] + y2[j][1]*y2[j][1];
                }
                ss += __shfl_xor_sync(0xffffffffu, ss, 1);
                ss += __shfl_xor_sync(0xffffffffu, ss, 2);
                float rr = rsqrtf(ss * (1.f / 64.f) + 1e-5f);
                if (mode == 0) rr *= qsc;
#pragma unroll
                for (int j = 0; j < 4; j++) {
                    drow[j * 8 + pa]       = tf32f(y1[j][0] * rr);
                    drow[j * 8 + pb_]      = tf32f(y1[j][1] * rr);
                    drow[j * 8 + 32 + pa]  = tf32f(y2[j][0] * rr);
                    drow[j * 8 + 32 + pb_] = tf32f(y2[j][1] * rr);
                }
            }
        }
    }
}

// ---------------- attention: flash, tf32 mma.sync, P via register shuffles ----------------
// smem = double-buffered K+V only (73.7 KB) -> 3 CTAs/SM; regs capped at 170.
#define AQ 128
#define AK 64
#define KSTR 72
#define VSTR 72
#define KBUF (64*KSTR)
#define VBUF (64*VSTR)
#define AK_OFF(st) ((st) * KBUF)
#define AV_OFF(st) (2*KBUF + (st) * VBUF)
#define ASMEM ((2*KBUF + 2*VBUF) * 4)   // 73728 bytes

__global__ __launch_bounds__(128, 3) void attn_mma()
{
    extern __shared__ float smf[];
    const uint32_t smem_base = smem_to_u32(smf);
    const int tid  = threadIdx.x;
    const int w    = tid >> 5;
    const int lane = tid & 31;
    const int gr   = lane >> 2;
    const int gc   = lane & 3;

    const int bh = blockIdx.y;
    const int q0 = blockIdx.x * AQ + w * 32;

    const float* Qg = g_qh + ((size_t)bh * T_ + q0) * D_;
    const float* Kg = g_kh + (size_t)bh * T_ * D_;
    const float* Vg = g_vh + (size_t)bh * D_ * T_;

    const int arow = tid >> 4;
    const int aseg = tid & 15;

    auto issue_kv = [&](int tile, int st) {
        const int s0 = tile * AK;
#pragma unroll
        for (int p = 0; p < 8; p++) {
            const int r = arow + p * 8;
            cp16(smem_base + (AK_OFF(st) + r * KSTR) * 4 + aseg * 16,
                 Kg + (size_t)(s0 + r) * D_ + aseg * 4);
            cp16(smem_base + (AV_OFF(st) + r * VSTR) * 4 + aseg * 16,
                 Vg + (size_t)r * T_ + s0 + aseg * 4);
        }
    };

    // Q fragments (persist whole kernel)
    unsigned qa[2][8][4];
#pragma unroll
    for (int hm = 0; hm < 2; hm++) {
        const float* qr0 = Qg + (hm*16 + gr) * D_;
        const float* qr1 = qr0 + 8 * D_;
#pragma unroll
        for (int kc = 0; kc < 8; kc++) {
            const float2 p0 = *(const float2*)(qr0 + kc*8 + 2*gc);
            const float2 p1 = *(const float2*)(qr1 + kc*8 + 2*gc);
            qa[hm][kc][0] = __float_as_uint(p0.x);
            qa[hm][kc][1] = __float_as_uint(p1.x);
            qa[hm][kc][2] = __float_as_uint(p0.y);
            qa[hm][kc][3] = __float_as_uint(p1.y);
        }
    }

    float o[2][8][4];
#pragma unroll
    for (int hm = 0; hm < 2; hm++)
#pragma unroll
        for (int nt = 0; nt < 8; nt++)
#pragma unroll
            for (int j = 0; j < 4; j++) o[hm][nt][j] = 0.f;

    float lrow[2][2] = {{0.f, 0.f}, {0.f, 0.f}};

    // shfl source lanes for C->A relayout (within quad)
    const int src0 = (lane & ~3) | (gc >> 1);
    const int src1 = src0 + 2;
    const bool odd = (gc & 1);

    issue_kv(0, 0); CP_COMMIT();

    const int NT = T_ / AK;
    for (int tile = 0; tile < NT; tile++) {
        const int st = tile & 1;
        if (tile + 1 < NT) { issue_kv(tile + 1, st ^ 1); CP_COMMIT(); CP_WAIT1(); }
        else               { CP_WAIT0(); }
        __syncthreads();

        const float* Ks = smf + AK_OFF(st);
        const float* Vs = smf + AV_OFF(st);

        // stream per key-chunk: QK -> softmax -> shfl relayout -> PV
#pragma unroll
        for (int nt = 0; nt < 8; nt++) {
            // K fragments for this key-chunk
            const float* kb = Ks + (nt*8 + gr) * KSTR + 2*gc;
            unsigned bl[8][2];
#pragma unroll
            for (int kc = 0; kc < 8; kc++) {
                const uint2 bb = *(const uint2*)(kb + kc*8);
                bl[kc][0] = bb.x;
                bl[kc][1] = bb.y;
            }

            float sv0[4] = {0.f, 0.f, 0.f, 0.f};
            float sv1[4] = {0.f, 0.f, 0.f, 0.f};
#pragma unroll
            for (int kc = 0; kc < 8; kc++) mma8(sv0, qa[0][kc], bl[kc][0], bl[kc][1]);
#pragma unroll
            for (int kc = 0; kc < 8; kc++) mma8(sv1, qa[1][kc], bl[kc][0], bl[kc][1]);

            // softmax (max-free) + tf32 round
            unsigned p0[4], p1[4];
            {
                const float e00 = ex2f(sv0[0]), e01 = ex2f(sv0[1]);
                const float e02 = ex2f(sv0[2]), e03 = ex2f(sv0[3]);
                lrow[0][0] += e00 + e01;
                lrow[0][1] += e02 + e03;
                p0[0] = cvt_tf32(e00); p0[1] = cvt_tf32(e01);
                p0[2] = cvt_tf32(e02); p0[3] = cvt_tf32(e03);
                const float e10 = ex2f(sv1[0]), e11 = ex2f(sv1[1]);
                const float e12 = ex2f(sv1[2]), e13 = ex2f(sv1[3]);
                lrow[1][0] += e10 + e11;
                lrow[1][1] += e12 + e13;
                p1[0] = cvt_tf32(e10); p1[1] = cvt_tf32(e11);
                p1[2] = cvt_tf32(e12); p1[3] = cvt_tf32(e13);
            }

            // C-frag -> A-frag relayout via shuffles
            unsigned a0[4], a1[4];
            {
                unsigned u0 = __shfl_sync(0xffffffffu, p0[0], src0);
                unsigned u1 = __shfl_sync(0xffffffffu, p0[1], src0);
                unsigned u2 = __shfl_sync(0xffffffffu, p0[0], src1);
                unsigned u3 = __shfl_sync(0xffffffffu, p0[1], src1);
                a0[0] = odd ? u1 : u0;
                a0[2] = odd ? u3 : u2;
                unsigned v0 = __shfl_sync(0xffffffffu, p0[2], src0);
                unsigned v1 = __shfl_sync(0xffffffffu, p0[3], src0);
                unsigned v2 = __shfl_sync(0xffffffffu, p0[2], src1);
                unsigned v3 = __shfl_sync(0xffffffffu, p0[3], src1);
                a0[1] = odd ? v1 : v0;
                a0[3] = odd ? v3 : v2;
            }
            {
                unsigned u0 = __shfl_sync(0xffffffffu, p1[0], src0);
                unsigned u1 = __shfl_sync(0xffffffffu, p1[1], src0);
                unsigned u2 = __shfl_sync(0xffffffffu, p1[0], src1);
                unsigned u3 = __shfl_sync(0xffffffffu, p1[1], src1);
                a1[0] = odd ? u1 : u0;
                a1[2] = odd ? u3 : u2;
                unsigned v0 = __shfl_sync(0xffffffffu, p1[2], src0);
                unsigned v1 = __shfl_sync(0xffffffffu, p1[3], src0);
                unsigned v2 = __shfl_sync(0xffffffffu, p1[2], src1);
                unsigned v3 = __shfl_sync(0xffffffffu, p1[3], src1);
                a1[1] = odd ? v1 : v0;
                a1[3] = odd ? v3 : v2;
            }

            // PV for this key-chunk over all d-chunks
#pragma unroll
            for (int dt = 0; dt < 8; dt++) {
                const uint2 vv = *(const uint2*)(Vs + (dt*8 + gr) * VSTR + nt*8 + 2*gc);
                mma8(o[0][dt], a0, vv.x, vv.y);
                mma8(o[1][dt], a1, vv.x, vv.y);
            }
        }
        __syncthreads();
    }

#pragma unroll
    for (int hm = 0; hm < 2; hm++)
#pragma unroll
        for (int off = 1; off <= 2; off <<= 1) {
            lrow[hm][0] += __shfl_xor_sync(0xffffffffu, lrow[hm][0], off);
            lrow[hm][1] += __shfl_xor_sync(0xffffffffu, lrow[hm][1], off);
        }

    const int b = bh / H_;
    const int h = bh % H_;
#pragma unroll
    for (int hm = 0; hm < 2; hm++) {
        const float il0 = 1.f / lrow[hm][0];
        const float il1 = 1.f / lrow[hm][1];
        const int r0 = q0 + hm*16 + gr;
        const int r1 = r0 + 8;
#pragma unroll
        for (int nt = 0; nt < 8; nt++) {
            const int col = h * D_ + nt*8 + 2*gc;
            *(float2*)(g_yt + (size_t)(b * T_ + r0) * C_ + col) =
                make_float2(tf32f(o[hm][nt][0] * il0), tf32f(o[hm][nt][1] * il0));
            *(float2*)(g_yt + (size_t)(b * T_ + r1) * C_ + col) =
                make_float2(tf32f(o[hm][nt][2] * il1), tf32f(o[hm][nt][3] * il1));
        }
    }
}

// ---------------- launch ----------------
extern "C" void kernel_launch(void* const* d_in, const int* in_sizes, int n_in,
                              void* d_out, int out_size)
{
    const float* x    = (const float*)d_in[0];
    const float* Wq   = (const float*)d_in[1];
    const float* Wk   = (const float*)d_in[2];
    const float* Wv   = (const float*)d_in[3];
    const float* Wo   = (const float*)d_in[4];
    const float* cosp = (const float*)d_in[5];
    const float* sinp = (const float*)d_in[6];
    float* out = (float*)d_out;

    void *p_xc, *p_w3, *p_wo, *p_yt;
    cudaGetSymbolAddress(&p_xc, g_xc);
    cudaGetSymbolAddress(&p_w3, g_w3);
    cudaGetSymbolAddress(&p_wo, g_wo);
    cudaGetSymbolAddress(&p_yt, g_yt);

    static int attrs_set = 0;
    if (!attrs_set) {
        cudaFuncSetAttribute(attn_mma, cudaFuncAttributeMaxDynamicSharedMemorySize, ASMEM);
        cudaFuncSetAttribute(gemm_pipe, cudaFuncAttributeMaxDynamicSharedMemorySize, GSMEM);
        attrs_set = 1;
    }

    float* w3 = (float*)p_w3;

    const int nx4 = MC_ / 4;
    const int nw4 = CC_ / 4;
    cvt_kernel<<<(nx4 + 255) / 256, 256>>>((const float4*)x, (float4*)p_xc, nx4);
    cvt4_kernel<<<(nw4 + 255) / 256, 256>>>(
        (const float4*)Wq, (const float4*)Wk, (const float4*)Wv, (const float4*)Wo,
        (float4*)w3, (float4*)(w3 + CC_), (float4*)(w3 + 2*CC_), (float4*)p_wo, nw4);

    // QKV projections with fused rope/rms/transpose epilogue
    dim3 gq(C_/128, M_/128, 3);       // (3, 128, 3)
    gemm_pipe<<<gq, 128, GSMEM>>>((const float*)p_xc, w3, nullptr, cosp, sinp, CC_, 0);

    dim3 ga(T_ / AQ, B_ * H_);        // (16, 48)
    attn_mma<<<ga, 128, ASMEM>>>();

    // output projection (plain epilogue)
    dim3 go(C_/128, M_/128, 1);
    gemm_pipe<<<go, 128, GSMEM>>>((const float*)p_yt, (const float*)p_wo, out,
                                  cosp, sinp, 0, 3);
}

// round 15
// speedup vs baseline: 1.0763x; 1.0763x over previous
#include <cuda_runtime.h>
#include <math.h>
#include <stdint.h>

// Problem constants
#define B_ 8
#define T_ 2048
#define C_ 384
#define H_ 6
#define D_ 64
#define M_ (B_*T_)          // 16384 rows
#define HALF_ 32            // D/2
#define MC_ (M_*C_)
#define CC_ (C_*C_)

// ---------------- tf32 helpers ----------------
__device__ __forceinline__ unsigned cvt_tf32(float x) {
    unsigned u;
    asm("cvt.rna.tf32.f32 %0, %1;" : "=r"(u) : "f"(x));
    return u;
}
__device__ __forceinline__ float tf32f(float x) {
    return __uint_as_float(cvt_tf32(x));
}
__device__ __forceinline__ float ex2f(float x) {
    float y;
    asm("ex2.approx.f32 %0, %1;" : "=f"(y) : "f"(x));
    return y;
}
__device__ __forceinline__ void mma8(float c[4], const unsigned a[4],
                                     unsigned b0, unsigned b1) {
    asm volatile(
        "mma.sync.aligned.m16n8k8.row.col.f32.tf32.tf32.f32 "
        "{%0,%1,%2,%3}, {%4,%5,%6,%7}, {%8,%9}, {%0,%1,%2,%3};"
        : "+f"(c[0]), "+f"(c[1]), "+f"(c[2]), "+f"(c[3])
        : "r"(a[0]), "r"(a[1]), "r"(a[2]), "r"(a[3]), "r"(b0), "r"(b1));
}
__device__ __forceinline__ void cp16(uint32_t dst, const void* src) {
    asm volatile("cp.async.cg.shared.global [%0], [%1], 16;" :: "r"(dst), "l"(src));
}
#define CP_COMMIT() asm volatile("cp.async.commit_group;" ::: "memory")
#define CP_WAIT1()  asm volatile("cp.async.wait_group 1;"  ::: "memory")
#define CP_WAIT0()  asm volatile("cp.async.wait_group 0;"  ::: "memory")
__device__ __forceinline__ uint32_t smem_to_u32(const void* p) {
    uint32_t a;
    asm("{ .reg .u64 t; cvta.to.shared.u64 t, %1; cvt.u32.u64 %0, t; }"
        : "=r"(a) : "l"(p));
    return a;
}

// ---------------- scratch ----------------
__device__ float g_xc[(size_t)MC_];          // tf32-rounded x
__device__ float g_w3[(size_t)3*CC_];        // tf32-rounded Wq,Wk,Wv stacked
__device__ float g_wo[(size_t)CC_];          // tf32-rounded Wo
__device__ float g_qh[(size_t)B_*H_*T_*D_];  // [bh][t][dperm]
__device__ float g_kh[(size_t)B_*H_*T_*D_];  // [bh][t][dperm]
__device__ float g_vh[(size_t)B_*H_*T_*D_];  // TRANSPOSED: [bh][d][keyperm]
__device__ float g_yt[(size_t)MC_];          // attention out (tf32-rounded)

// ---------------- elementwise tf32 pre-convert ----------------
__global__ __launch_bounds__(256) void cvt_kernel(const float4* __restrict__ src,
                                                  float4* __restrict__ dst, int n4)
{
    const int i = blockIdx.x * blockDim.x + threadIdx.x;
    if (i < n4) {
        const float4 v = src[i];
        dst[i] = make_float4(tf32f(v.x), tf32f(v.y), tf32f(v.z), tf32f(v.w));
    }
}

__global__ __launch_bounds__(256) void cvt4_kernel(const float4* __restrict__ s0,
                                                   const float4* __restrict__ s1,
                                                   const float4* __restrict__ s2,
                                                   const float4* __restrict__ s3,
                                                   float4* __restrict__ d0,
                                                   float4* __restrict__ d1,
                                                   float4* __restrict__ d2,
                                                   float4* __restrict__ d3,
                                                   int n4)
{
    const int i = blockIdx.x * blockDim.x + threadIdx.x;
    if (i < n4) {
        float4 v;
        v = s0[i]; d0[i] = make_float4(tf32f(v.x), tf32f(v.y), tf32f(v.z), tf32f(v.w));
        v = s1[i]; d1[i] = make_float4(tf32f(v.x), tf32f(v.y), tf32f(v.z), tf32f(v.w));
        v = s2[i]; d2[i] = make_float4(tf32f(v.x), tf32f(v.y), tf32f(v.z), tf32f(v.w));
        v = s3[i]; d3[i] = make_float4(tf32f(v.x), tf32f(v.y), tf32f(v.z), tf32f(v.w));
    }
}

// ---------------- pipelined tf32 GEMM with fused rope/rms epilogue ----------------
// mode 0/1: rope+rms(+qscale) -> g_qh/g_kh (d-pair interleaved), smem-staged stores
// mode 2:   tf32 transpose -> g_vh [bh][d][keyperm], smem-staged stores
// mode 3:   plain fp32 row-major -> Cb
#define TBK 32
#define NCH (C_ / TBK)          // 12
#define SSTR 36
#define STAGE_BYTES (128 * SSTR * 4)          // 18432
#define GA_OFF(st) ((st) * STAGE_BYTES)
#define GB_OFF(st) (2 * STAGE_BYTES + (st) * STAGE_BYTES)
#define GSMEM (4 * STAGE_BYTES)               // 73728
#define QKSTG 68                              // staging row stride (Q/K): 2*128*68*4 = 69632
#define VSTG 132                              // staging row stride (V): 2*64*132*4 = 67584

__global__ __launch_bounds__(128) void gemm_pipe(const float* __restrict__ A,
                                                 const float* __restrict__ W,
                                                 float* __restrict__ Cb,
                                                 const float* __restrict__ cosp,
                                                 const float* __restrict__ sinp,
                                                 int wstride, int mode_base)
{
    extern __shared__ char smem[];
    const uint32_t smem_base = smem_to_u32(smem);
    float* smf = (float*)smem;

    const int tid  = threadIdx.x;
    const int w    = tid >> 5;
    const int lane = tid & 31;
    const int gr   = lane >> 2;
    const int gc   = lane & 3;
    const int wm   = w >> 1;
    const int wn   = w & 1;

    const int m0 = blockIdx.y * 128;
    const int n0 = blockIdx.x * 128;
    const int z  = blockIdx.z;
    const int mode = (mode_base == 3) ? 3 : z;
    const float* Wz = W + (size_t)z * wstride;

    float acc[4][8][4];
#pragma unroll
    for (int i = 0; i < 4; i++)
#pragma unroll
        for (int j = 0; j < 8; j++)
#pragma unroll
            for (int r = 0; r < 4; r++) acc[i][j][r] = 0.f;

    auto issue = [&](int ch, int st) {
#pragma unroll
        for (int p = 0; p < 8; p++) {
            const int idx = p * 128 + tid;
            const int r = idx >> 3;
            const int s = idx & 7;
            const uint32_t doff = r * (SSTR * 4) + s * 16;
            cp16(smem_base + GA_OFF(st) + doff,
                 A  + (size_t)(m0 + r) * C_ + ch * TBK + s * 4);
            cp16(smem_base + GB_OFF(st) + doff,
                 Wz + (size_t)(n0 + r) * C_ + ch * TBK + s * 4);
        }
    };

    issue(0, 0); CP_COMMIT();

    for (int ch = 0; ch < NCH; ch++) {
        const int st = ch & 1;
        if (ch + 1 < NCH) { issue(ch + 1, st ^ 1); CP_COMMIT(); CP_WAIT1(); }
        else              { CP_WAIT0(); }
        __syncthreads();

        const unsigned* sAf = (const unsigned*)(smem + GA_OFF(st));
        const unsigned* sBf = (const unsigned*)(smem + GB_OFF(st));

#pragma unroll
        for (int s = 0; s < 4; s++) {
            unsigned a[4][4];
#pragma unroll
            for (int i = 0; i < 4; i++) {
                const int row = wm * 64 + i * 16 + gr;
                a[i][0] = sAf[row * SSTR + s * 8 + gc];
                a[i][1] = sAf[(row + 8) * SSTR + s * 8 + gc];
                a[i][2] = sAf[row * SSTR + s * 8 + gc + 4];
                a[i][3] = sAf[(row + 8) * SSTR + s * 8 + gc + 4];
            }
            unsigned b[8][2];
#pragma unroll
            for (int j = 0; j < 8; j++) {
                const int row = wn * 64 + j * 8 + gr;
                b[j][0] = sBf[row * SSTR + s * 8 + gc];
                b[j][1] = sBf[row * SSTR + s * 8 + gc + 4];
            }
#pragma unroll
            for (int i = 0; i < 4; i++)
#pragma unroll
                for (int j = 0; j < 8; j++)
                    mma8(acc[i][j], a[i], b[j][0], b[j][1]);
        }
        __syncthreads();
    }
    // stage smem is now dead -> reuse for epilogue staging

    if (mode == 3) {
#pragma unroll
        for (int i = 0; i < 4; i++) {
#pragma unroll
            for (int j = 0; j < 8; j++) {
                const int r  = m0 + wm * 64 + i * 16 + gr;
                const int cc = n0 + wn * 64 + j * 8 + gc * 2;
                *(float2*)(Cb + (size_t)r * C_ + cc)       = make_float2(acc[i][j][0], acc[i][j][1]);
                *(float2*)(Cb + (size_t)(r + 8) * C_ + cc) = make_float2(acc[i][j][2], acc[i][j][3]);
            }
        }
        return;
    }

    const int hb = blockIdx.x * 2;               // first head of this CTA
    const float qsc = 0.125f * 1.44269504088896340736f;
    const int pa  = (gc < 2) ? (4 * gc)     : (4 * gc - 7);  // pi(2gc)
    const int pb_ = (gc < 2) ? (4 * gc + 2) : (4 * gc - 5);  // pi(2gc+1)
    const int pgr = (gr < 4) ? (2 * gr) : (2 * gr - 7);      // pi(gr)

    // ---- write phase: compute + stage into smem ----
#pragma unroll
    for (int i = 0; i < 4; i++) {
#pragma unroll
        for (int sub = 0; sub < 2; sub++) {
            const int rloc = wm * 64 + i * 16 + gr + sub * 8;   // 0..127
            const int t = (m0 + rloc) % T_;
            const int e0 = sub * 2;

            if (mode == 2) {
                // stage [head][d][key_local] rows of 128, stride VSTG
                const int Uloc = rloc - gr + pgr;
                float* vb2 = smf + (size_t)(wn * 64) * VSTG;
#pragma unroll
                for (int j = 0; j < 8; j++) {
                    const int d = j * 8 + 2 * gc;
                    vb2[(size_t)d * VSTG + Uloc]       = tf32f(acc[i][j][e0]);
                    vb2[(size_t)(d + 1) * VSTG + Uloc] = tf32f(acc[i][j][e0 + 1]);
                }
            } else {
                float* drow = smf + (size_t)(wn * 128 + rloc) * QKSTG;
                float y1[4][2], y2[4][2];
                float ss = 0.f;
#pragma unroll
                for (int j = 0; j < 4; j++) {
                    const int d = j * 8 + 2 * gc;
                    const float c0 = cosp[t * HALF_ + d];
                    const float c1 = cosp[t * HALF_ + d + 1];
                    const float s0 = sinp[t * HALF_ + d];
                    const float s1 = sinp[t * HALF_ + d + 1];
                    const float x10 = acc[i][j][e0],     x11 = acc[i][j][e0 + 1];
                    const float x20 = acc[i][j + 4][e0], x21 = acc[i][j + 4][e0 + 1];
                    y1[j][0] =  x10 * c0 + x20 * s0;
                    y1[j][1] =  x11 * c1 + x21 * s1;
                    y2[j][0] = -x10 * s0 + x20 * c0;
                    y2[j][1] = -x11 * s1 + x21 * c1;
                    ss += y1[j][0]*y1[j][0] + y1[j][1]*y1[j][1]
                        + y2[j][0]*y2[j][0] + y2[j][1]*y2[j][1];
                }
                ss += __shfl_xor_sync(0xffffffffu, ss, 1);
                ss += __shfl_xor_sync(0xffffffffu, ss, 2);
                float rr = rsqrtf(ss * (1.f / 64.f) + 1e-5f);
                if (mode == 0) rr *= qsc;
#pragma unroll
                for (int j = 0; j < 4; j++) {
                    drow[j * 8 + pa]       = tf32f(y1[j][0] * rr);
                    drow[j * 8 + pb_]      = tf32f(y1[j][1] * rr);
                    drow[j * 8 + 32 + pa]  = tf32f(y2[j][0] * rr);
                    drow[j * 8 + 32 + pb_] = tf32f(y2[j][1] * rr);
                }
            }
        }
    }
    __syncthreads();

    // ---- copy phase: coalesced float4 stores ----
    if (mode == 2) {
        // 128 rows (2 heads x 64 d) x 128 keys; 32 segs/row; 16 threads... 32 consecutive
        const int b = m0 / T_;
        const int t0 = m0 % T_;
#pragma unroll
        for (int q = 0; q < 32; q++) {
            const int idx = q * 128 + tid;
            const int row = idx >> 5;           // 0..127
            const int seg = idx & 31;
            const float4 v = *(const float4*)(smf + (size_t)row * VSTG + seg * 4);
            const int head = row >> 6;
            const int d = row & 63;
            *(float4*)(g_vh + ((size_t)(b * H_ + hb + head) * D_ + d) * T_ + t0 + seg * 4) = v;
        }
    } else {
        float* dst = (mode == 0) ? g_qh : g_kh;
#pragma unroll
        for (int q = 0; q < 32; q++) {
            const int idx = q * 128 + tid;
            const int row = idx >> 4;           // 0..255
            const int seg = idx & 15;
            const float4 v = *(const float4*)(smf + (size_t)row * QKSTG + seg * 4);
            const int head = row >> 7;
            const int rloc = row & 127;
            const int gidx = m0 + rloc;
            const int b = gidx / T_;
            const int t = gidx % T_;
            *(float4*)(dst + ((size_t)(b * H_ + hb + head) * T_ + t) * D_ + seg * 4) = v;
        }
    }
}

// ---------------- attention: flash, tf32 mma.sync (round-13 proven) ----------------
#define AQ 128
#define AK 64
#define KSTR 72
#define VSTR 72
#define PSTR 68
#define KBUF (64*KSTR)
#define VBUF (64*VSTR)
#define AK_OFF(st) ((st) * KBUF)
#define AV_OFF(st) (2*KBUF + (st) * VBUF)
#define AP_OFF     (2*KBUF + 2*VBUF)
#define ASMEM ((2*KBUF + 2*VBUF + 4*32*PSTR) * 4)   // 108544 bytes

__global__ __launch_bounds__(128) void attn_mma()
{
    extern __shared__ float smf[];
    const uint32_t smem_base = smem_to_u32(smf);
    const int tid  = threadIdx.x;
    const int w    = tid >> 5;
    const int lane = tid & 31;
    const int gr   = lane >> 2;
    const int gc   = lane & 3;
    float* Ps = smf + AP_OFF + w * (32*PSTR);

    const int bh = blockIdx.y;
    const int q0 = blockIdx.x * AQ + w * 32;

    const float* Qg = g_qh + ((size_t)bh * T_ + q0) * D_;
    const float* Kg = g_kh + (size_t)bh * T_ * D_;
    const float* Vg = g_vh + (size_t)bh * D_ * T_;

    const int arow = tid >> 4;
    const int aseg = tid & 15;

    auto issue_kv = [&](int tile, int st) {
        const int s0 = tile * AK;
#pragma unroll
        for (int p = 0; p < 8; p++) {
            const int r = arow + p * 8;
            cp16(smem_base + (AK_OFF(st) + r * KSTR) * 4 + aseg * 16,
                 Kg + (size_t)(s0 + r) * D_ + aseg * 4);
            cp16(smem_base + (AV_OFF(st) + r * VSTR) * 4 + aseg * 16,
                 Vg + (size_t)r * T_ + s0 + aseg * 4);
        }
    };

    unsigned qa[2][8][4];
#pragma unroll
    for (int hm = 0; hm < 2; hm++) {
        const float* qr0 = Qg + (hm*16 + gr) * D_;
        const float* qr1 = qr0 + 8 * D_;
#pragma unroll
        for (int kc = 0; kc < 8; kc++) {
            const float2 p0 = *(const float2*)(qr0 + kc*8 + 2*gc);
            const float2 p1 = *(const float2*)(qr1 + kc*8 + 2*gc);
            qa[hm][kc][0] = __float_as_uint(p0.x);
            qa[hm][kc][1] = __float_as_uint(p1.x);
            qa[hm][kc][2] = __float_as_uint(p0.y);
            qa[hm][kc][3] = __float_as_uint(p1.y);
        }
    }

    float o[2][8][4];
#pragma unroll
    for (int hm = 0; hm < 2; hm++)
#pragma unroll
        for (int nt = 0; nt < 8; nt++)
#pragma unroll
            for (int j = 0; j < 4; j++) o[hm][nt][j] = 0.f;

    float lrow[2][2] = {{0.f, 0.f}, {0.f, 0.f}};

    issue_kv(0, 0); CP_COMMIT();

    const int NT = T_ / AK;
    for (int tile = 0; tile < NT; tile++) {
        const int st = tile & 1;
        if (tile + 1 < NT) { issue_kv(tile + 1, st ^ 1); CP_COMMIT(); CP_WAIT1(); }
        else               { CP_WAIT0(); }
        __syncthreads();

        const float* Ks = smf + AK_OFF(st);
        const float* Vs = smf + AV_OFF(st);

        float sv[2][8][4];
#pragma unroll
        for (int hm = 0; hm < 2; hm++)
#pragma unroll
            for (int nt = 0; nt < 8; nt++)
#pragma unroll
                for (int j = 0; j < 4; j++) sv[hm][nt][j] = 0.f;

#pragma unroll
        for (int nt = 0; nt < 8; nt++) {
            const float* kb = Ks + (nt*8 + gr) * KSTR + 2*gc;
            unsigned bl[8][2];
#pragma unroll
            for (int kc = 0; kc < 8; kc++) {
                const uint2 bb = *(const uint2*)(kb + kc*8);
                bl[kc][0] = bb.x;
                bl[kc][1] = bb.y;
            }
#pragma unroll
            for (int kc = 0; kc < 8; kc++) mma8(sv[0][nt], qa[0][kc], bl[kc][0], bl[kc][1]);
#pragma unroll
            for (int kc = 0; kc < 8; kc++) mma8(sv[1][nt], qa[1][kc], bl[kc][0], bl[kc][1]);
        }

#pragma unroll
        for (int hm = 0; hm < 2; hm++) {
#pragma unroll
            for (int nt = 0; nt < 8; nt++) {
                const float p00 = ex2f(sv[hm][nt][0]);
                const float p01 = ex2f(sv[hm][nt][1]);
                const float p10 = ex2f(sv[hm][nt][2]);
                const float p11 = ex2f(sv[hm][nt][3]);
                lrow[hm][0] += p00 + p01;
                lrow[hm][1] += p10 + p11;
                float* pr0 = Ps + (hm*16 + gr) * PSTR + nt*8 + 2*gc;
                pr0[0] = tf32f(p00); pr0[1] = tf32f(p01);
                float* pr1 = pr0 + 8 * PSTR;
                pr1[0] = tf32f(p10); pr1[1] = tf32f(p11);
            }
        }
        __syncwarp();

#pragma unroll
        for (int kc = 0; kc < 8; kc++) {
            unsigned a0[4], a1[4];
            const float* pb = Ps + gr * PSTR + kc*8 + gc;
            a0[0] = __float_as_uint(pb[0]);
            a0[1] = __float_as_uint(pb[8*PSTR]);
            a0[2] = __float_as_uint(pb[4]);
            a0[3] = __float_as_uint(pb[8*PSTR + 4]);
            const float* pb1 = pb + 16*PSTR;
            a1[0] = __float_as_uint(pb1[0]);
            a1[1] = __float_as_uint(pb1[8*PSTR]);
            a1[2] = __float_as_uint(pb1[4]);
            a1[3] = __float_as_uint(pb1[8*PSTR + 4]);
#pragma unroll
            for (int nt = 0; nt < 8; nt++) {
                const uint2 vv = *(const uint2*)(Vs + (nt*8 + gr) * VSTR + kc*8 + 2*gc);
                mma8(o[0][nt], a0, vv.x, vv.y);
                mma8(o[1][nt], a1, vv.x, vv.y);
            }
        }
        __syncthreads();
    }

#pragma unroll
    for (int hm = 0; hm < 2; hm++)
#pragma unroll
        for (int off = 1; off <= 2; off <<= 1) {
            lrow[hm][0] += __shfl_xor_sync(0xffffffffu, lrow[hm][0], off);
            lrow[hm][1] += __shfl_xor_sync(0xffffffffu, lrow[hm][1], off);
        }

    const int b = bh / H_;
    const int h = bh % H_;
#pragma unroll
    for (int hm = 0; hm < 2; hm++) {
        const float il0 = 1.f / lrow[hm][0];
        const float il1 = 1.f / lrow[hm][1];
        const int r0 = q0 + hm*16 + gr;
        const int r1 = r0 + 8;
#pragma unroll
        for (int nt = 0; nt < 8; nt++) {
            const int col = h * D_ + nt*8 + 2*gc;
            *(float2*)(g_yt + (size_t)(b * T_ + r0) * C_ + col) =
                make_float2(tf32f(o[hm][nt][0] * il0), tf32f(o[hm][nt][1] * il0));
            *(float2*)(g_yt + (size_t)(b * T_ + r1) * C_ + col) =
                make_float2(tf32f(o[hm][nt][2] * il1), tf32f(o[hm][nt][3] * il1));
        }
    }
}

// ---------------- launch ----------------
extern "C" void kernel_launch(void* const* d_in, const int* in_sizes, int n_in,
                              void* d_out, int out_size)
{
    const float* x    = (const float*)d_in[0];
    const float* Wq   = (const float*)d_in[1];
    const float* Wk   = (const float*)d_in[2];
    const float* Wv   = (const float*)d_in[3];
    const float* Wo   = (const float*)d_in[4];
    const float* cosp = (const float*)d_in[5];
    const float* sinp = (const float*)d_in[6];
    float* out = (float*)d_out;

    void *p_xc, *p_w3, *p_wo, *p_yt;
    cudaGetSymbolAddress(&p_xc, g_xc);
    cudaGetSymbolAddress(&p_w3, g_w3);
    cudaGetSymbolAddress(&p_wo, g_wo);
    cudaGetSymbolAddress(&p_yt, g_yt);

    static int attrs_set = 0;
    if (!attrs_set) {
        cudaFuncSetAttribute(attn_mma, cudaFuncAttributeMaxDynamicSharedMemorySize, ASMEM);
        cudaFuncSetAttribute(gemm_pipe, cudaFuncAttributeMaxDynamicSharedMemorySize, GSMEM);
        attrs_set = 1;
    }

    float* w3 = (float*)p_w3;

    const int nx4 = MC_ / 4;
    const int nw4 = CC_ / 4;
    cvt_kernel<<<(nx4 + 255) / 256, 256>>>((const float4*)x, (float4*)p_xc, nx4);
    cvt4_kernel<<<(nw4 + 255) / 256, 256>>>(
        (const float4*)Wq, (const float4*)Wk, (const float4*)Wv, (const float4*)Wo,
        (float4*)w3, (float4*)(w3 + CC_), (float4*)(w3 + 2*CC_), (float4*)p_wo, nw4);

    // QKV projections with fused rope/rms/transpose epilogue (smem-staged stores)
    dim3 gq(C_/128, M_/128, 3);       // (3, 128, 3)
    gemm_pipe<<<gq, 128, GSMEM>>>((const float*)p_xc, w3, nullptr, cosp, sinp, CC_, 0);

    dim3 ga(T_ / AQ, B_ * H_);        // (16, 48)
    attn_mma<<<ga, 128, ASMEM>>>();

    // output projection (plain epilogue)
    dim3 go(C_/128, M_/128, 1);
    gemm_pipe<<<go, 128, GSMEM>>>((const float*)p_yt, (const float*)p_wo, out,
                                  cosp, sinp, 0, 3);
}